// round 1
// baseline (speedup 1.0000x reference)
#include <cuda_runtime.h>
#include <math.h>

#define D_DET   363
#define N_ANG   360
#define IMG     256
#define PAD     76
#define STRIDE  544          // padded row stride: [0,76) zeros, [76,439) data, [439,544) zeros
#define NROWS   720          // B * N_ANG

// ---- device scratch (no allocations allowed) ----
__device__ float  g_h2[728];                 // doubled ramp kernel h2[j] = h[(j-362) mod D], j in [0,724]
__device__ float2 g_trig[N_ANG];             // (cos*c1, sin*c1) per angle
__device__ float  g_filt[NROWS * STRIDE];    // zero-padded filtered sinogram

// ============================================================================
// Kernel 1: prep — closed-form ramp impulse response + trig table
//   h[n] = (1/D) sum_k filt[k] e^{2pi i k n / D}, filt[k] = 2*min(k,D-k)/D
//        = (4/D^2) sum_{k=1..M} k cos(k*theta),  D = 2M+1, theta = 2*pi*n/D
//   sum_{k=1..M} k cos(k t) = ((M+1)cos(Mt) - M cos((M+1)t) - 1) / (4 sin^2(t/2))
// ============================================================================
__global__ void prep_kernel() {
    int t = threadIdx.x;
    if (t < D_DET) {
        const double Dd = (double)D_DET;
        const int    M  = (D_DET - 1) / 2;   // 181
        double h;
        if (t == 0) {
            h = 2.0 * (double)M * (double)(M + 1) / (Dd * Dd);
        } else {
            double th  = 2.0 * M_PI * (double)t / Dd;
            double s   = sin(0.5 * th);
            double num = (double)(M + 1) * cos((double)M * th)
                       - (double)M       * cos((double)(M + 1) * th) - 1.0;
            h = num / (Dd * Dd * s * s);
        }
        float hf = (float)h;
        // h2[j] = h[(j - 362) mod D]:  h2[t+362] = h[t];  h2[t-1] = h[t] for t>=1
        g_h2[t + 362] = hf;
        if (t >= 1) g_h2[t - 1] = hf;
    }
    if (t < N_ANG) {
        double ang = (double)t * (M_PI / 360.0);             // linspace(0, pi*(1-1/A), A)
        // scale = (H-1)/2 * sqrt(2) / ((D-1)/2);  c1 = (D-1)/(2*scale)
        double c1 = 181.0 * 181.0 / (127.5 * sqrt(2.0));
        g_trig[t] = make_float2((float)(cos(ang) * c1), (float)(sin(ang) * c1));
    }
}

// ============================================================================
// Kernel 2: circular convolution (exact equivalent of fft-ramp-ifft.real),
// writing into the zero-padded layout. One block per (b,angle) row.
// ============================================================================
__global__ __launch_bounds__(576) void filter_kernel(const float* __restrict__ sino) {
    __shared__ float s_row[D_DET];
    __shared__ float s_h2[726];
    int row = blockIdx.x;              // 0..719
    int t   = threadIdx.x;             // 0..575

    for (int i = t; i < D_DET; i += 576) s_row[i] = sino[row * D_DET + i];
    for (int i = t; i < 725;   i += 576) s_h2[i]  = g_h2[i];
    __syncthreads();

    if (t < STRIDE) {
        float val = 0.0f;
        int d = t - PAD;
        if ((unsigned)d < (unsigned)D_DET) {
            // filtered[d] = sum_k s[k] * h[(d-k) mod D] = sum_k s[k] * h2[d - k + 362]
            const float* hp = s_h2 + d + 362;
            float acc = 0.0f;
            #pragma unroll 11
            for (int k = 0; k < D_DET; k++)
                acc = fmaf(s_row[k], hp[-k], acc);
            val = acc;
        }
        g_filt[row * STRIDE + t] = val;
    }
}

// ============================================================================
// Kernel 3: backprojection. 16x16 pixel tile per block, loop over 360 angles.
// Zero padding removes all bounds checks: u+PAD in [0.07, 513.93] always.
// ============================================================================
__global__ __launch_bounds__(256) void bp_kernel(float* __restrict__ out) {
    __shared__ float2 s_trig[N_ANG];
    int tid = threadIdx.y * 16 + threadIdx.x;
    for (int i = tid; i < N_ANG; i += 256) s_trig[i] = g_trig[i];
    __syncthreads();

    int b = blockIdx.z;
    int x = blockIdx.x * 16 + threadIdx.x;
    int y = blockIdx.y * 16 + threadIdx.y;
    float xf = fmaf((float)x, 2.0f / 255.0f, -1.0f);
    float yf = fmaf((float)y, 2.0f / 255.0f, -1.0f);

    const float* rowp = g_filt + b * (N_ANG * STRIDE);
    const float uc = (float)(PAD + 181);   // 257: detector center + pad offset

    float acc = 0.0f;
    #pragma unroll 4
    for (int a = 0; a < N_ANG; a++) {
        float2 cs = s_trig[a];
        float u  = fmaf(xf, cs.x, fmaf(yf, cs.y, uc));
        float uf = floorf(u);
        int   i0 = (int)uf;
        float w1 = u - uf;
        const float* r = rowp + i0;
        float v0 = __ldg(r);
        float v1 = __ldg(r + 1);
        acc = fmaf(w1, v1 - v0, acc + v0);   // v0*(1-w1) + v1*w1
        rowp += STRIDE;
    }

    out[b * (IMG * IMG) + y * IMG + x] = acc * (float)(M_PI / 360.0);
}

// ============================================================================
extern "C" void kernel_launch(void* const* d_in, const int* in_sizes, int n_in,
                              void* d_out, int out_size) {
    const float* sino = (const float*)d_in[0];   // (2,1,360,363) float32
    float* out = (float*)d_out;                  // (2,1,256,256) float32

    prep_kernel<<<1, 384>>>();
    filter_kernel<<<NROWS, 576>>>(sino);
    bp_kernel<<<dim3(IMG / 16, IMG / 16, 2), dim3(16, 16)>>>(out);
}

// round 7
// speedup vs baseline: 1.3198x; 1.3198x over previous
#include <cuda_runtime.h>
#include <math.h>

#define D_DET   363
#define N_ANG   360
#define IMG     256
#define PAD     76
#define STRIDE  544                    // padded row length (floats)
#define NROWS   720                    // B * N_ANG

// Zero-padded filtered sinogram (scalar, R1-proven layout)
__device__ float g_filt[NROWS * STRIDE];

// ============================================================================
// Kernel 1: ramp-filter via exact circular convolution (== ifft(fft*2|f|).real)
// 2 rows per block, 96 threads/row. h table computed in-block (float closed
// form, cospif with exact integer mod-726 reduction). 4 outputs per thread
// with a sliding h-window (0.5 LDS per FMA).
// ============================================================================
__global__ __launch_bounds__(192) void filter_kernel(const float* __restrict__ sino) {
    __shared__ float s_h2[736];        // s_h2[j+4] = h[(j-362) mod 363], zeros elsewhere
    __shared__ float s_row[2][368];
    __shared__ float s_out[2][546];    // full padded rows (zeros in pads)

    int t = threadIdx.x;               // 0..191
    int r = t / 96;                    // local row
    int j = t - r * 96;
    int row0 = blockIdx.x * 2;

    // ---- build h2 table ----
    // h[n] = (182 cos(362 n pi/363) - 181 cos(364 n pi/363) - 1) / (363^2 sin^2(n pi/363))
    for (int i = t; i < 736; i += 192) {
        float v = 0.0f;
        int jj = i - 4;
        if (jj >= 0 && jj <= 724) {
            int n = (jj >= 362) ? (jj - 362) : (jj + 1);   // (jj-362) mod 363
            if (n == 0) {
                v = 2.0f * 181.0f * 182.0f / (363.0f * 363.0f);
            } else {
                int r1 = (362 * n) % 726;                  // exact mod-2pi reduction
                int r2 = (364 * n) % 726;
                float c1 = cospif((float)r1 * (1.0f / 363.0f));
                float c2 = cospif((float)r2 * (1.0f / 363.0f));
                float s  = sinpif((float)n  * (1.0f / 363.0f));
                v = (182.0f * c1 - 181.0f * c2 - 1.0f) / (363.0f * 363.0f * s * s);
            }
        }
        s_h2[i] = v;
    }
    // ---- load input rows ----
    for (int i = t; i < 2 * 368; i += 192) {
        int rr = i / 368, c = i - rr * 368;
        s_row[rr][c] = (c < D_DET) ? sino[(row0 + rr) * D_DET + c] : 0.0f;
    }
    // ---- zero padded output rows ----
    for (int i = t; i < 2 * 546; i += 192) ((float*)s_out)[i] = 0.0f;
    __syncthreads();

    // ---- convolution: outputs d0..d0+3, h window slides one element per k ----
    if (j < 91) {
        int d0 = 4 * j;                          // 0..360
        const float* sr = s_row[r];
        int base = 366 + d0;                     // = 362 + d0 + 4 (table offset)
        float w0 = s_h2[base + 0];
        float w1 = s_h2[base + 1];
        float w2 = s_h2[base + 2];
        float w3 = s_h2[base + 3];
        float a0 = 0.f, a1 = 0.f, a2 = 0.f, a3 = 0.f;
        #pragma unroll 4
        for (int k = 0; k < D_DET; k++) {
            float sv = sr[k];
            a0 = fmaf(sv, w0, a0);
            a1 = fmaf(sv, w1, a1);
            a2 = fmaf(sv, w2, a2);
            a3 = fmaf(sv, w3, a3);
            w3 = w2; w2 = w1; w1 = w0;
            w0 = s_h2[base - 1 - k];             // min index 3: in-bounds
        }
        s_out[r][PAD + d0 + 0] = a0;
        s_out[r][PAD + d0 + 1] = a1;
        s_out[r][PAD + d0 + 2] = a2;
        if (d0 + 3 < D_DET) s_out[r][PAD + d0 + 3] = a3;
    }
    __syncthreads();

    // ---- write scalar padded rows ----
    for (int i = t; i < 2 * STRIDE; i += 192) {
        int rr = i / STRIDE, c = i - rr * STRIDE;
        g_filt[(row0 + rr) * STRIDE + c] = s_out[rr][c];
    }
}

// ============================================================================
// Kernel 2: backprojection — VERBATIM the R1 kernel that passed (16x16 tile,
// floorf, two scalar __ldg). Only change: trig table built here (sincospif)
// instead of the eliminated double-precision prep kernel.
// ============================================================================
__global__ __launch_bounds__(256) void bp_kernel(float* __restrict__ out) {
    __shared__ float2 s_trig[N_ANG];
    int tid = threadIdx.y * 16 + threadIdx.x;

    const float C1 = 32761.0f / (127.5f * 1.41421356237309515f);  // 181^2/(127.5*sqrt2)
    for (int a = tid; a < N_ANG; a += 256) {
        float sa, ca;
        sincospif((float)a * (1.0f / 360.0f), &sa, &ca);          // angle = a*pi/360
        s_trig[a] = make_float2(ca * C1, sa * C1);
    }
    __syncthreads();

    int b = blockIdx.z;
    int x = blockIdx.x * 16 + threadIdx.x;
    int y = blockIdx.y * 16 + threadIdx.y;
    float xf = fmaf((float)x, 2.0f / 255.0f, -1.0f);
    float yf = fmaf((float)y, 2.0f / 255.0f, -1.0f);

    const float* rowp = g_filt + b * (N_ANG * STRIDE);
    const float uc = (float)(PAD + 181);   // 257: detector center + pad offset

    float acc = 0.0f;
    #pragma unroll 4
    for (int a = 0; a < N_ANG; a++) {
        float2 cs = s_trig[a];
        float u  = fmaf(xf, cs.x, fmaf(yf, cs.y, uc));
        float uf = floorf(u);
        int   i0 = (int)uf;
        float w1 = u - uf;
        const float* r = rowp + i0;
        float v0 = __ldg(r);
        float v1 = __ldg(r + 1);
        acc = fmaf(w1, v1 - v0, acc + v0);   // v0*(1-w1) + v1*w1
        rowp += STRIDE;
    }

    out[b * (IMG * IMG) + y * IMG + x] = acc * (float)(M_PI / 360.0);
}

// ============================================================================
extern "C" void kernel_launch(void* const* d_in, const int* in_sizes, int n_in,
                              void* d_out, int out_size) {
    const float* sino = (const float*)d_in[0];   // (2,1,360,363) float32
    float* out = (float*)d_out;                  // (2,1,256,256) float32

    filter_kernel<<<NROWS / 2, 192>>>(sino);
    bp_kernel<<<dim3(IMG / 16, IMG / 16, 2), dim3(16, 16)>>>(out);
}